// round 8
// baseline (speedup 1.0000x reference)
#include <cuda_runtime.h>
#include <math.h>

// ---------------------------------------------------------------------------
// TinyViT block, fp32 baseline for GB300 (sm_103a).
// Shapes fixed by the problem: B=64, H=W=28, C=384, HEADS=12, WS=7, KD=32.
// ---------------------------------------------------------------------------

#define BB      64
#define HH      28
#define WWID    28
#define CC      384
#define HEADS   12
#define WS      7
#define KD      32
#define NWIN    49
#define MLPH    1536
#define LTOK    784                 // H*W
#define MTOK    (BB * LTOK)         // 50176 tokens
#define NWIN_TOT (BB * 16)          // 1024 windows (4x4 per image)
#define EPSV    1e-5f
#define SCALEQ  0.17677669529663687f  // 32^-0.5

// Scratch (allocation-guard-safe: __device__ globals)
__device__ float g_buf0[MTOK * MLPH];   // qkv (stride 1152) then fc1 output (stride 1536)
__device__ float g_buf1[MTOK * CC];     // xn (LN1) then xn2 (LN2)
__device__ float g_buf2[MTOK * CC];     // attn out, then conv+bn output x2
__device__ float g_buf3[MTOK * CC];     // x1 = x + proj(attn)

__device__ __forceinline__ float gelu_f(float v) {
    return 0.5f * v * (1.0f + erff(v * 0.7071067811865475f));
}

// ---------------------------------------------------------------------------
// LayerNorm: one warp per token, C=384 = 3 float4 per lane.
// ---------------------------------------------------------------------------
__global__ __launch_bounds__(256)
void ln_kernel(const float* __restrict__ x, const float* __restrict__ g,
               const float* __restrict__ b, float* __restrict__ y)
{
    int gt   = blockIdx.x * (blockDim.x >> 5) + (threadIdx.x >> 5);
    int lane = threadIdx.x & 31;
    if (gt >= MTOK) return;

    const float4* xr = (const float4*)(x + (size_t)gt * CC);
    const float4* gr = (const float4*)g;
    const float4* br = (const float4*)b;

    float4 v[3];
    float s = 0.f, s2 = 0.f;
#pragma unroll
    for (int i = 0; i < 3; i++) {
        v[i] = xr[lane + 32 * i];
        s  += v[i].x + v[i].y + v[i].z + v[i].w;
        s2 += v[i].x * v[i].x + v[i].y * v[i].y + v[i].z * v[i].z + v[i].w * v[i].w;
    }
#pragma unroll
    for (int o = 16; o > 0; o >>= 1) {
        s  += __shfl_xor_sync(0xffffffffu, s,  o);
        s2 += __shfl_xor_sync(0xffffffffu, s2, o);
    }
    float mean = s * (1.f / CC);
    float var  = s2 * (1.f / CC) - mean * mean;
    float rstd = rsqrtf(var + EPSV);

    float4* yr = (float4*)(y + (size_t)gt * CC);
#pragma unroll
    for (int i = 0; i < 3; i++) {
        float4 gg = gr[lane + 32 * i], bb = br[lane + 32 * i], o;
        o.x = (v[i].x - mean) * rstd * gg.x + bb.x;
        o.y = (v[i].y - mean) * rstd * gg.y + bb.y;
        o.z = (v[i].z - mean) * rstd * gg.z + bb.z;
        o.w = (v[i].w - mean) * rstd * gg.w + bb.w;
        yr[lane + 32 * i] = o;
    }
}

// ---------------------------------------------------------------------------
// SGEMM: C[M,N] = A[M,K] * W[N,K]^T (+bias [+res] [gelu]).
// 128x128 block tile, BK=8, 256 threads, 8x8 per-thread microtile.
// All dims here are exact multiples of the tile (no bounds checks).
// MODE: 0 = +bias, 1 = +bias+res, 2 = gelu(+bias)
// ---------------------------------------------------------------------------
template<int MODE>
__global__ __launch_bounds__(256, 2)
void sgemm_kernel(const float* __restrict__ A, const float* __restrict__ W,
                  const float* __restrict__ bias, const float* __restrict__ res,
                  float* __restrict__ Cmat, int Ndim, int Kdim)
{
    __shared__ float As[8][128];
    __shared__ float Bs[8][128];

    int tid = threadIdx.x;
    int bn = blockIdx.x, bm = blockIdx.y;

    const float* Ab = A + (size_t)bm * 128 * Kdim;
    const float* Wb = W + (size_t)bn * 128 * Kdim;

    int lr = tid >> 1;            // 0..127 : tile row to load
    int lk = (tid & 1) << 2;      // 0 or 4 : k sub-offset
    int tx = tid & 15;
    int ty = tid >> 4;

    float acc[8][8];
#pragma unroll
    for (int i = 0; i < 8; i++)
#pragma unroll
        for (int j = 0; j < 8; j++) acc[i][j] = 0.f;

    const float* aptr = Ab + (size_t)lr * Kdim + lk;
    const float* wptr = Wb + (size_t)lr * Kdim + lk;

    for (int k0 = 0; k0 < Kdim; k0 += 8) {
        float4 a4 = *(const float4*)(aptr + k0);
        float4 w4 = *(const float4*)(wptr + k0);
        __syncthreads();
        As[lk + 0][lr] = a4.x; As[lk + 1][lr] = a4.y;
        As[lk + 2][lr] = a4.z; As[lk + 3][lr] = a4.w;
        Bs[lk + 0][lr] = w4.x; Bs[lk + 1][lr] = w4.y;
        Bs[lk + 2][lr] = w4.z; Bs[lk + 3][lr] = w4.w;
        __syncthreads();
#pragma unroll
        for (int kk = 0; kk < 8; kk++) {
            float4 a0 = *(const float4*)&As[kk][ty * 4];
            float4 a1 = *(const float4*)&As[kk][64 + ty * 4];
            float4 b0 = *(const float4*)&Bs[kk][tx * 4];
            float4 b1 = *(const float4*)&Bs[kk][64 + tx * 4];
            float ar[8] = {a0.x, a0.y, a0.z, a0.w, a1.x, a1.y, a1.z, a1.w};
            float br_[8] = {b0.x, b0.y, b0.z, b0.w, b1.x, b1.y, b1.z, b1.w};
#pragma unroll
            for (int i = 0; i < 8; i++)
#pragma unroll
                for (int j = 0; j < 8; j++) acc[i][j] += ar[i] * br_[j];
        }
    }

    // epilogue
#pragma unroll
    for (int ri = 0; ri < 8; ri++) {
        int r = (ri < 4) ? (ty * 4 + ri) : (64 + ty * 4 + (ri - 4));
        size_t m = (size_t)bm * 128 + r;
        float* crow = Cmat + m * Ndim + (size_t)bn * 128;
#pragma unroll
        for (int half = 0; half < 2; half++) {
            int c = half ? (64 + tx * 4) : (tx * 4);
            float4 v;
            v.x = acc[ri][half * 4 + 0];
            v.y = acc[ri][half * 4 + 1];
            v.z = acc[ri][half * 4 + 2];
            v.w = acc[ri][half * 4 + 3];
            float4 bb = *(const float4*)(bias + bn * 128 + c);
            v.x += bb.x; v.y += bb.y; v.z += bb.z; v.w += bb.w;
            if (MODE == 1) {
                float4 rr = *(const float4*)(res + m * Ndim + bn * 128 + c);
                v.x += rr.x; v.y += rr.y; v.z += rr.z; v.w += rr.w;
            }
            if (MODE == 2) {
                v.x = gelu_f(v.x); v.y = gelu_f(v.y);
                v.z = gelu_f(v.z); v.w = gelu_f(v.w);
            }
            *(float4*)(crow + c) = v;
        }
    }
}

// ---------------------------------------------------------------------------
// Window attention: one block per (window, head). 12288 blocks x 128 threads.
// qkv layout per token row (stride 1152): [head][q(32)|k(32)|v(32)].
// Output written directly back into natural token order (undoes window perm).
// ---------------------------------------------------------------------------
#define QKPAD 36   // row stride for q/k/v smem (kills stride-128B bank conflicts)

__global__ __launch_bounds__(128)
void attn_kernel(const float* __restrict__ qkv, const float* __restrict__ attn_bias,
                 const int* __restrict__ bias_idxs, float* __restrict__ att)
{
    __shared__ float qs[NWIN][QKPAD];
    __shared__ float ks[NWIN][QKPAD];
    __shared__ float vs[NWIN][QKPAD];
    __shared__ float Ss[NWIN][NWIN];   // odd row stride 49 -> conflict-free columns
    __shared__ int   rowb[NWIN];

    int blk = blockIdx.x;
    int h   = blk % HEADS;
    int win = blk / HEADS;
    int b   = win >> 4;
    int wr  = win & 15;
    int wh  = wr >> 2, ww = wr & 3;
    int tid = threadIdx.x;

    if (tid < NWIN) {
        int i = tid / WS, j = tid - i * WS;
        rowb[tid] = b * LTOK + (wh * WS + i) * WWID + (ww * WS + j);
    }
    __syncthreads();

    // gather q,k,v for this (window, head): 49 tokens x 24 float4
    for (int idx = tid; idx < NWIN * 24; idx += 128) {
        int p = idx / 24, q4 = idx - p * 24;
        const float4* src = (const float4*)(qkv + (size_t)rowb[p] * 1152 + h * 96);
        float4 val = src[q4];
        float* dst = (q4 < 8)  ? &qs[p][q4 * 4]
                   : (q4 < 16) ? &ks[p][(q4 - 8) * 4]
                               : &vs[p][(q4 - 16) * 4];
        dst[0] = val.x; dst[1] = val.y; dst[2] = val.z; dst[3] = val.w;
    }
    __syncthreads();

    // S = q k^T * scale + bias
    const float* brow = attn_bias + h * NWIN;  // 49 relative-offset slots
    for (int e = tid; e < NWIN * NWIN; e += 128) {
        int i = e / NWIN, j = e - i * NWIN;
        const float4* qi = (const float4*)qs[i];
        const float4* kj = (const float4*)ks[j];
        float acc = 0.f;
#pragma unroll
        for (int t = 0; t < 8; t++) {
            float4 a = qi[t], c = kj[t];
            acc += a.x * c.x + a.y * c.y + a.z * c.z + a.w * c.w;
        }
        Ss[i][j] = acc * SCALEQ + brow[bias_idxs[e]];
    }
    __syncthreads();

    // row softmax (one lane per row)
    if (tid < NWIN) {
        float m = -1e30f;
        for (int j = 0; j < NWIN; j++) m = fmaxf(m, Ss[tid][j]);
        float s = 0.f;
        for (int j = 0; j < NWIN; j++) {
            float e = expf(Ss[tid][j] - m);
            Ss[tid][j] = e;
            s += e;
        }
        float inv = 1.f / s;
        for (int j = 0; j < NWIN; j++) Ss[tid][j] *= inv;
    }
    __syncthreads();

    // O = P V, written straight to natural token order, col = h*32 + d
    for (int e = tid; e < NWIN * 8; e += 128) {
        int i = e >> 3, d4 = e & 7;
        float4 acc = make_float4(0.f, 0.f, 0.f, 0.f);
        for (int j = 0; j < NWIN; j++) {
            float p = Ss[i][j];
            float4 vv = *(const float4*)&vs[j][d4 * 4];
            acc.x += p * vv.x; acc.y += p * vv.y;
            acc.z += p * vv.z; acc.w += p * vv.w;
        }
        *(float4*)(att + (size_t)rowb[i] * CC + h * KD + d4 * 4) = acc;
    }
}

// ---------------------------------------------------------------------------
// Depthwise 3x3 conv (SAME, zero pad) + BatchNorm, channels-last float4.
// One thread per (pixel, 4-channel group). Fully coalesced.
// ---------------------------------------------------------------------------
__global__ __launch_bounds__(256)
void conv_bn_kernel(const float* __restrict__ xin, const float* __restrict__ w,
                    const float* __restrict__ bng, const float* __restrict__ bnb,
                    const float* __restrict__ bnm, const float* __restrict__ bnv,
                    float* __restrict__ out)
{
    int idx = blockIdx.x * blockDim.x + threadIdx.x;
    if (idx >= MTOK * 96) return;
    int c4  = idx % 96;
    int pix = idx / 96;
    int b = pix / LTOK;
    int l = pix - b * LTOK;
    int y = l / WWID;
    int xw = l - y * WWID;
    int cbase = c4 * 4;

    const float4* in4 = (const float4*)xin;
    float a0 = 0.f, a1 = 0.f, a2 = 0.f, a3 = 0.f;
#pragma unroll
    for (int dy = -1; dy <= 1; dy++) {
        int yy = y + dy;
        if ((unsigned)yy >= (unsigned)HH) continue;
#pragma unroll
        for (int dx = -1; dx <= 1; dx++) {
            int xx = xw + dx;
            if ((unsigned)xx >= (unsigned)WWID) continue;
            float4 v = in4[((size_t)b * LTOK + yy * WWID + xx) * 96 + c4];
            int tap = (dy + 1) * 3 + (dx + 1);
            a0 += v.x * w[(cbase + 0) * 9 + tap];
            a1 += v.y * w[(cbase + 1) * 9 + tap];
            a2 += v.z * w[(cbase + 2) * 9 + tap];
            a3 += v.w * w[(cbase + 3) * 9 + tap];
        }
    }
    float4 o;
    o.x = (a0 - bnm[cbase + 0]) * rsqrtf(bnv[cbase + 0] + EPSV) * bng[cbase + 0] + bnb[cbase + 0];
    o.y = (a1 - bnm[cbase + 1]) * rsqrtf(bnv[cbase + 1] + EPSV) * bng[cbase + 1] + bnb[cbase + 1];
    o.z = (a2 - bnm[cbase + 2]) * rsqrtf(bnv[cbase + 2] + EPSV) * bng[cbase + 2] + bnb[cbase + 2];
    o.w = (a3 - bnm[cbase + 3]) * rsqrtf(bnv[cbase + 3] + EPSV) * bng[cbase + 3] + bnb[cbase + 3];
    ((float4*)out)[(size_t)pix * 96 + c4] = o;
}

// ---------------------------------------------------------------------------
// Launcher (graph-capturable: kernels only, no sync / no alloc).
// Input order per metadata.txt = setup_inputs dict order.
// ---------------------------------------------------------------------------
extern "C" void kernel_launch(void* const* d_in, const int* in_sizes, int n_in,
                              void* d_out, int out_size)
{
    const float* x      = (const float*)d_in[0];
    const float* n1g    = (const float*)d_in[1];
    const float* n1b    = (const float*)d_in[2];
    const float* qkv_w  = (const float*)d_in[3];
    const float* qkv_b  = (const float*)d_in[4];
    const float* attn_b = (const float*)d_in[5];
    const int*   bidx   = (const int*)  d_in[6];
    const float* proj_w = (const float*)d_in[7];
    const float* proj_b = (const float*)d_in[8];
    const float* conv_w = (const float*)d_in[9];
    const float* bn_g   = (const float*)d_in[10];
    const float* bn_b   = (const float*)d_in[11];
    const float* bn_m   = (const float*)d_in[12];
    const float* bn_v   = (const float*)d_in[13];
    const float* n2g    = (const float*)d_in[14];
    const float* n2b    = (const float*)d_in[15];
    const float* fc1_w  = (const float*)d_in[16];
    const float* fc1_b  = (const float*)d_in[17];
    const float* fc2_w  = (const float*)d_in[18];
    const float* fc2_b  = (const float*)d_in[19];
    float* out = (float*)d_out;

    void *p0, *p1, *p2, *p3;
    cudaGetSymbolAddress(&p0, g_buf0);
    cudaGetSymbolAddress(&p1, g_buf1);
    cudaGetSymbolAddress(&p2, g_buf2);
    cudaGetSymbolAddress(&p3, g_buf3);
    float* b0 = (float*)p0;
    float* b1 = (float*)p1;
    float* b2 = (float*)p2;
    float* b3 = (float*)p3;

    // 1. LN1: x -> b1
    ln_kernel<<<MTOK / 8, 256>>>(x, n1g, n1b, b1);

    // 2. QKV: b1[50176,384] @ qkv_w[1152,384]^T + bias -> b0 (stride 1152)
    {
        dim3 g(1152 / 128, MTOK / 128);
        sgemm_kernel<0><<<g, 256>>>(b1, qkv_w, qkv_b, nullptr, b0, 1152, CC);
    }

    // 3. Window attention: b0 -> b2 (natural token order, stride 384)
    attn_kernel<<<NWIN_TOT * HEADS, 128>>>(b0, attn_b, bidx, b2);

    // 4. Proj + residual x: b2 @ proj_w^T + proj_b + x -> b3
    {
        dim3 g(CC / 128, MTOK / 128);
        sgemm_kernel<1><<<g, 256>>>(b2, proj_w, proj_b, x, b3, CC, CC);
    }

    // 5. Depthwise conv 3x3 + BN: b3 -> b2
    conv_bn_kernel<<<(MTOK * 96 + 255) / 256, 256>>>(b3, conv_w, bn_g, bn_b, bn_m, bn_v, b2);

    // 6. LN2: b2 -> b1
    ln_kernel<<<MTOK / 8, 256>>>(b2, n2g, n2b, b1);

    // 7. FC1 + exact GELU: b1 @ fc1_w^T + fc1_b -> b0 (stride 1536)
    {
        dim3 g(MLPH / 128, MTOK / 128);
        sgemm_kernel<2><<<g, 256>>>(b1, fc1_w, fc1_b, nullptr, b0, MLPH, CC);
    }

    // 8. FC2 + bias + residual b2 -> d_out
    {
        dim3 g(CC / 128, MTOK / 128);
        sgemm_kernel<1><<<g, 256>>>(b0, fc2_w, fc2_b, b2, out, CC, MLPH);
    }
}

// round 16
// speedup vs baseline: 1.8376x; 1.8376x over previous
#include <cuda_runtime.h>
#include <cuda_bf16.h>
#include <math.h>
#include <stdint.h>

// ---------------------------------------------------------------------------
// TinyViT block on GB300 (sm_103 target): mma.sync bf16 hi/lo-split GEMMs.
// B=64, H=W=28, C=384, HEADS=12, WS=7, KD=32.
// tcgen05 is unavailable (harness compiles for plain sm_103, no 'a' feature),
// so tensor work goes through mma.sync.m16n8k16 (HMMA path).
// ---------------------------------------------------------------------------

#define BB      64
#define HH      28
#define WWID    28
#define CC      384
#define HEADS   12
#define WS      7
#define KD      32
#define NWIN    49
#define MLPH    1536
#define LTOK    784
#define MTOK    (BB * LTOK)          // 50176
#define EPSV    1e-5f
#define SCALEQ  0.17677669529663687f

// ---------------- scratch (__device__ globals: allocation-guard-safe) ------
__device__ float          g_qkv[(size_t)MTOK * 1152];
__device__ unsigned short g_xh [(size_t)MTOK * CC];
__device__ unsigned short g_xl [(size_t)MTOK * CC];
__device__ unsigned short g_ath[(size_t)MTOK * CC];
__device__ unsigned short g_atl[(size_t)MTOK * CC];
__device__ unsigned short g_hh [(size_t)MTOK * MLPH];
__device__ unsigned short g_hl [(size_t)MTOK * MLPH];
__device__ float          g_x1 [(size_t)MTOK * CC];
__device__ float          g_x2 [(size_t)MTOK * CC];
__device__ unsigned short g_qwh[1152 * CC], g_qwl[1152 * CC];
__device__ unsigned short g_pwh[CC * CC],   g_pwl[CC * CC];
__device__ unsigned short g_f1h[MLPH * CC], g_f1l[MLPH * CC];
__device__ unsigned short g_f2h[CC * MLPH], g_f2l[CC * MLPH];

// ---------------- small helpers --------------------------------------------
__device__ __forceinline__ float gelu_f(float v) {
    return 0.5f * v * (1.0f + erff(v * 0.7071067811865475f));
}
__device__ __forceinline__ void split1(float v, unsigned short& h, unsigned short& l) {
    __nv_bfloat16 hb = __float2bfloat16(v);
    __nv_bfloat16 lb = __float2bfloat16(v - __bfloat162float(hb));
    h = __bfloat16_as_ushort(hb);
    l = __bfloat16_as_ushort(lb);
}
__device__ __forceinline__ uint32_t smem_u32(const void* p) {
    uint32_t a;
    asm("{ .reg .u64 t; cvta.to.shared.u64 t, %1; cvt.u32.u64 %0, t; }"
        : "=r"(a) : "l"(p));
    return a;
}
__device__ __forceinline__ void cpasync16(uint32_t dst, const void* src) {
    asm volatile("cp.async.cg.shared.global [%0], [%1], 16;"
                 :: "r"(dst), "l"(src) : "memory");
}
__device__ __forceinline__ void ldsm4(uint32_t& r0, uint32_t& r1,
                                      uint32_t& r2, uint32_t& r3, uint32_t addr) {
    asm volatile("ldmatrix.sync.aligned.m8n8.x4.shared.b16 {%0,%1,%2,%3}, [%4];"
                 : "=r"(r0), "=r"(r1), "=r"(r2), "=r"(r3) : "r"(addr));
}
__device__ __forceinline__ void mma16816(float* c, uint32_t a0, uint32_t a1,
                                         uint32_t a2, uint32_t a3,
                                         uint32_t b0, uint32_t b1) {
    asm volatile(
        "mma.sync.aligned.m16n8k16.row.col.f32.bf16.bf16.f32 "
        "{%0,%1,%2,%3},{%4,%5,%6,%7},{%8,%9},{%0,%1,%2,%3};"
        : "+f"(c[0]), "+f"(c[1]), "+f"(c[2]), "+f"(c[3])
        : "r"(a0), "r"(a1), "r"(a2), "r"(a3), "r"(b0), "r"(b1));
}

// ---------------------------------------------------------------------------
// Weight split: fp32 -> bf16 hi + bf16 lo
// ---------------------------------------------------------------------------
__global__ __launch_bounds__(256)
void split_kernel(const float* __restrict__ in, unsigned short* __restrict__ hi,
                  unsigned short* __restrict__ lo, int n)
{
    int i = blockIdx.x * 256 + threadIdx.x;
    if (i < n) {
        unsigned short h, l;
        split1(in[i], h, l);
        hi[i] = h; lo[i] = l;
    }
}

// ---------------------------------------------------------------------------
// LayerNorm -> bf16 hi/lo split. One warp per token, C=384.
// ---------------------------------------------------------------------------
__global__ __launch_bounds__(256)
void ln_split_kernel(const float* __restrict__ x, const float* __restrict__ g,
                     const float* __restrict__ b, unsigned short* __restrict__ yh,
                     unsigned short* __restrict__ yl)
{
    int gt   = blockIdx.x * 8 + (threadIdx.x >> 5);
    int lane = threadIdx.x & 31;
    if (gt >= MTOK) return;

    const float4* xr = (const float4*)(x + (size_t)gt * CC);
    const float4* gr = (const float4*)g;
    const float4* br = (const float4*)b;

    float4 v[3];
    float s = 0.f, s2 = 0.f;
#pragma unroll
    for (int i = 0; i < 3; i++) {
        v[i] = xr[lane + 32 * i];
        s  += v[i].x + v[i].y + v[i].z + v[i].w;
        s2 += v[i].x * v[i].x + v[i].y * v[i].y + v[i].z * v[i].z + v[i].w * v[i].w;
    }
#pragma unroll
    for (int o = 16; o > 0; o >>= 1) {
        s  += __shfl_xor_sync(0xffffffffu, s,  o);
        s2 += __shfl_xor_sync(0xffffffffu, s2, o);
    }
    float mean = s * (1.f / CC);
    float rstd = rsqrtf(s2 * (1.f / CC) - mean * mean + EPSV);

    uint2* hr = (uint2*)(yh + (size_t)gt * CC);
    uint2* lr = (uint2*)(yl + (size_t)gt * CC);
#pragma unroll
    for (int i = 0; i < 3; i++) {
        float4 gg = gr[lane + 32 * i], bb = br[lane + 32 * i];
        float o0 = (v[i].x - mean) * rstd * gg.x + bb.x;
        float o1 = (v[i].y - mean) * rstd * gg.y + bb.y;
        float o2 = (v[i].z - mean) * rstd * gg.z + bb.z;
        float o3 = (v[i].w - mean) * rstd * gg.w + bb.w;
        unsigned short h0, l0, h1, l1, h2, l2, h3, l3;
        split1(o0, h0, l0); split1(o1, h1, l1);
        split1(o2, h2, l2); split1(o3, h3, l3);
        uint2 hv, lv;
        hv.x = (uint32_t)h0 | ((uint32_t)h1 << 16);
        hv.y = (uint32_t)h2 | ((uint32_t)h3 << 16);
        lv.x = (uint32_t)l0 | ((uint32_t)l1 << 16);
        lv.y = (uint32_t)l2 | ((uint32_t)l3 << 16);
        hr[lane + 32 * i] = hv;
        lr[lane + 32 * i] = lv;
    }
}

// ---------------------------------------------------------------------------
// mma.sync GEMM: C[M,N] = A[M,K] @ W[N,K]^T with bf16 hi/lo split (3 passes).
// Block tile 128x128, BK=32, 8 warps (2m x 4n), warp tile 64x32.
// Smem row stride 80B -> conflict-free ldmatrix. cp.async 2-stage pipeline.
// MODE 0: fp32 out = D + bias
// MODE 1: fp32 out = D + bias + res
// MODE 2: bf16 hi/lo out = split(gelu(D + bias))
// ---------------------------------------------------------------------------
#define ROWB   80                       // smem bytes per 32-element bf16 row
#define TILEB  (128 * ROWB)             // 10240 bytes per 128x32 tile
#define STAGEB (4 * TILEB)              // Ah, Al, Bh, Bl
#define GSMEM_SZ (2 * STAGEB)           // 81920 bytes

template<int MODE>
__global__ __launch_bounds__(256)
void tmma_gemm(const unsigned short* __restrict__ Ahi, const unsigned short* __restrict__ Alo,
               const unsigned short* __restrict__ Bhi, const unsigned short* __restrict__ Blo,
               const float* __restrict__ bias, const float* __restrict__ res,
               float* __restrict__ outF,
               unsigned short* __restrict__ outHi, unsigned short* __restrict__ outLo,
               int Ndim, int Kdim)
{
    extern __shared__ char gsm[];
    const uint32_t sb0 = smem_u32(gsm);

    const int tid  = threadIdx.x;
    const int wid  = tid >> 5, lane = tid & 31;
    const int bn   = blockIdx.x, bm = blockIdx.y;
    const int wm   = wid >> 2;          // 0..1  -> 64 rows each
    const int wn   = wid & 3;           // 0..3  -> 32 cols each

    const unsigned short* Ah = Ahi + (size_t)bm * 128 * Kdim;
    const unsigned short* Al = Alo + (size_t)bm * 128 * Kdim;
    const unsigned short* Bh = Bhi + (size_t)bn * 128 * Kdim;
    const unsigned short* Bl = Blo + (size_t)bn * 128 * Kdim;

    const int nch = Kdim >> 5;          // chunks of 32

    float acc[4][4][4];
#pragma unroll
    for (int i = 0; i < 4; i++)
#pragma unroll
        for (int j = 0; j < 4; j++)
#pragma unroll
            for (int t = 0; t < 4; t++) acc[i][j][t] = 0.f;

    // per-thread load slots: idx = tid + i*256 -> row = idx>>2, chunk = idx&3
    const int r0l = tid >> 2, ch0 = tid & 3;                // i = 0
    const int r1l = (tid + 256) >> 2, ch1 = ch0;            // i = 1

    // ldmatrix lane addressing
    const int lid8 = lane & 7, mid = lane >> 3;
    const int dm = (mid & 1) * 8, dk = (mid >> 1) * 8;

    // ---- issue loads for chunk c into buffer buf ----
    auto issue = [&](int c, int buf) {
        const uint32_t sb = sb0 + buf * STAGEB;
        const int k0 = c << 5;
        {
            uint32_t off = (uint32_t)(r0l * ROWB + ch0 * 16);
            size_t g = (size_t)r0l * Kdim + k0 + ch0 * 8;
            cpasync16(sb +             off, Ah + g);
            cpasync16(sb + TILEB     + off, Al + g);
            cpasync16(sb + 2 * TILEB + off, Bh + g);
            cpasync16(sb + 3 * TILEB + off, Bl + g);
        }
        {
            uint32_t off = (uint32_t)(r1l * ROWB + ch1 * 16);
            size_t g = (size_t)r1l * Kdim + k0 + ch1 * 8;
            cpasync16(sb +             off, Ah + g);
            cpasync16(sb + TILEB     + off, Al + g);
            cpasync16(sb + 2 * TILEB + off, Bh + g);
            cpasync16(sb + 3 * TILEB + off, Bl + g);
        }
        asm volatile("cp.async.commit_group;" ::: "memory");
    };

    issue(0, 0);

    for (int c = 0; c < nch; c++) {
        const int buf = c & 1;
        if (c + 1 < nch) {
            issue(c + 1, buf ^ 1);
            asm volatile("cp.async.wait_group 1;" ::: "memory");
        } else {
            asm volatile("cp.async.wait_group 0;" ::: "memory");
        }
        __syncthreads();

        const uint32_t sA = sb0 + buf * STAGEB;
        const uint32_t sAl = sA + TILEB;
        const uint32_t sBh = sA + 2 * TILEB;
        const uint32_t sBl = sA + 3 * TILEB;

#pragma unroll
        for (int ks = 0; ks < 2; ks++) {
            const int k0 = ks * 16;
            // B fragments for this warp's 32 columns (hi & lo)
            uint32_t bh[4][2], bl[4][2];
#pragma unroll
            for (int g = 0; g < 2; g++) {
                uint32_t off = (uint32_t)((wn * 32 + g * 16 + dm + lid8) * ROWB
                                          + (k0 + dk) * 2);
                uint32_t t0, t1, t2, t3;
                ldsm4(t0, t1, t2, t3, sBh + off);
                bh[g * 2 + 0][0] = t0; bh[g * 2 + 0][1] = t2;
                bh[g * 2 + 1][0] = t1; bh[g * 2 + 1][1] = t3;
                ldsm4(t0, t1, t2, t3, sBl + off);
                bl[g * 2 + 0][0] = t0; bl[g * 2 + 0][1] = t2;
                bl[g * 2 + 1][0] = t1; bl[g * 2 + 1][1] = t3;
            }
#pragma unroll
            for (int mf = 0; mf < 4; mf++) {
                uint32_t offA = (uint32_t)((wm * 64 + mf * 16 + dm + lid8) * ROWB
                                           + (k0 + dk) * 2);
                uint32_t a0, a1, a2, a3, l0, l1, l2, l3;
                ldsm4(a0, a1, a2, a3, sA  + offA);
                ldsm4(l0, l1, l2, l3, sAl + offA);
#pragma unroll
                for (int nf = 0; nf < 4; nf++) {
                    mma16816(acc[mf][nf], a0, a1, a2, a3, bh[nf][0], bh[nf][1]);
                    mma16816(acc[mf][nf], a0, a1, a2, a3, bl[nf][0], bl[nf][1]);
                    mma16816(acc[mf][nf], l0, l1, l2, l3, bh[nf][0], bh[nf][1]);
                }
            }
        }
        __syncthreads();
    }

    // ---- epilogue ----
#pragma unroll
    for (int mf = 0; mf < 4; mf++) {
        size_t r0 = (size_t)bm * 128 + wm * 64 + mf * 16 + (lane >> 2);
        size_t r1 = r0 + 8;
#pragma unroll
        for (int nf = 0; nf < 4; nf++) {
            int col = bn * 128 + wn * 32 + nf * 8 + (lane & 3) * 2;
            float b0 = bias[col], b1 = bias[col + 1];
            float v00 = acc[mf][nf][0] + b0, v01 = acc[mf][nf][1] + b1;
            float v10 = acc[mf][nf][2] + b0, v11 = acc[mf][nf][3] + b1;
            if (MODE == 1) {
                const float2 q0 = *(const float2*)(res + r0 * Ndim + col);
                const float2 q1 = *(const float2*)(res + r1 * Ndim + col);
                v00 += q0.x; v01 += q0.y; v10 += q1.x; v11 += q1.y;
            }
            if (MODE == 2) {
                v00 = gelu_f(v00); v01 = gelu_f(v01);
                v10 = gelu_f(v10); v11 = gelu_f(v11);
                unsigned short h00, q00, h01, q01, h10, q10, h11, q11;
                split1(v00, h00, q00); split1(v01, h01, q01);
                split1(v10, h10, q10); split1(v11, h11, q11);
                *(uint32_t*)(outHi + r0 * Ndim + col) = (uint32_t)h00 | ((uint32_t)h01 << 16);
                *(uint32_t*)(outLo + r0 * Ndim + col) = (uint32_t)q00 | ((uint32_t)q01 << 16);
                *(uint32_t*)(outHi + r1 * Ndim + col) = (uint32_t)h10 | ((uint32_t)h11 << 16);
                *(uint32_t*)(outLo + r1 * Ndim + col) = (uint32_t)q10 | ((uint32_t)q11 << 16);
            } else {
                float2 w0; w0.x = v00; w0.y = v01;
                float2 w1; w1.x = v10; w1.y = v11;
                *(float2*)(outF + r0 * Ndim + col) = w0;
                *(float2*)(outF + r1 * Ndim + col) = w1;
            }
        }
    }
}

// ---------------------------------------------------------------------------
// Window attention (fp32 math) -> bf16 hi/lo output. One block per (win,head).
// ---------------------------------------------------------------------------
#define QKPAD 36

__global__ __launch_bounds__(128)
void attn_kernel(const float* __restrict__ qkv, const float* __restrict__ attn_bias,
                 const int* __restrict__ bias_idxs,
                 unsigned short* __restrict__ att_h, unsigned short* __restrict__ att_l)
{
    __shared__ float qs[NWIN][QKPAD];
    __shared__ float ks[NWIN][QKPAD];
    __shared__ float vs[NWIN][QKPAD];
    __shared__ float Ss[NWIN][NWIN];
    __shared__ int   rowb[NWIN];

    int blk = blockIdx.x;
    int hd  = blk % HEADS;
    int win = blk / HEADS;
    int b   = win >> 4;
    int wr  = win & 15;
    int wh  = wr >> 2, ww = wr & 3;
    int tid = threadIdx.x;

    if (tid < NWIN) {
        int i = tid / WS, j = tid - i * WS;
        rowb[tid] = b * LTOK + (wh * WS + i) * WWID + (ww * WS + j);
    }
    __syncthreads();

    for (int idx = tid; idx < NWIN * 24; idx += 128) {
        int p = idx / 24, q4 = idx - p * 24;
        const float4* src = (const float4*)(qkv + (size_t)rowb[p] * 1152 + hd * 96);
        float4 val = src[q4];
        float* dst = (q4 < 8)  ? &qs[p][q4 * 4]
                   : (q4 < 16) ? &ks[p][(q4 - 8) * 4]
                               : &vs[p][(q4 - 16) * 4];
        dst[0] = val.x; dst[1] = val.y; dst[2] = val.z; dst[3] = val.w;
    }
    __syncthreads();

    const float* brow = attn_bias + hd * NWIN;
    for (int e = tid; e < NWIN * NWIN; e += 128) {
        int i = e / NWIN, j = e - i * NWIN;
        const float4* qi = (const float4*)qs[i];
        const float4* kj = (const float4*)ks[j];
        float acc = 0.f;
#pragma unroll
        for (int t = 0; t < 8; t++) {
            float4 a = qi[t], c = kj[t];
            acc += a.x * c.x + a.y * c.y + a.z * c.z + a.w * c.w;
        }
        Ss[i][j] = acc * SCALEQ + brow[bias_idxs[e]];
    }
    __syncthreads();

    if (tid < NWIN) {
        float mx = -1e30f;
        for (int j = 0; j < NWIN; j++) mx = fmaxf(mx, Ss[tid][j]);
        float s = 0.f;
        for (int j = 0; j < NWIN; j++) {
            float e = expf(Ss[tid][j] - mx);
            Ss[tid][j] = e;
            s += e;
        }
        float inv = 1.f / s;
        for (int j = 0; j < NWIN; j++) Ss[tid][j] *= inv;
    }
    __syncthreads();

    for (int e = tid; e < NWIN * 8; e += 128) {
        int i = e >> 3, d4 = e & 7;
        float4 acc = make_float4(0.f, 0.f, 0.f, 0.f);
        for (int j = 0; j < NWIN; j++) {
            float p = Ss[i][j];
            float4 vv = *(const float4*)&vs[j][d4 * 4];
            acc.x += p * vv.x; acc.y += p * vv.y;
            acc.z += p * vv.z; acc.w += p * vv.w;
        }
        unsigned short h0, l0, h1, l1, h2, l2, h3, l3;
        split1(acc.x, h0, l0); split1(acc.y, h1, l1);
        split1(acc.z, h2, l2); split1(acc.w, h3, l3);
        uint2 hv, lv;
        hv.x = (uint32_t)h0 | ((uint32_t)h1 << 16);
        hv.y = (uint32_t)h2 | ((uint32_t)h3 << 16);
        lv.x = (uint32_t)l0 | ((uint32_t)l1 << 16);
        lv.y = (uint32_t)l2 | ((uint32_t)l3 << 16);
        size_t base = (size_t)rowb[i] * CC + hd * KD;
        ((uint2*)(att_h + base))[d4] = hv;
        ((uint2*)(att_l + base))[d4] = lv;
    }
}

// ---------------------------------------------------------------------------
// Depthwise 3x3 conv (SAME) + BatchNorm, channels-last float4.
// ---------------------------------------------------------------------------
__global__ __launch_bounds__(256)
void conv_bn_kernel(const float* __restrict__ xin, const float* __restrict__ w,
                    const float* __restrict__ bng, const float* __restrict__ bnb,
                    const float* __restrict__ bnm, const float* __restrict__ bnv,
                    float* __restrict__ out)
{
    int idx = blockIdx.x * blockDim.x + threadIdx.x;
    if (idx >= MTOK * 96) return;
    int c4  = idx % 96;
    int pix = idx / 96;
    int b = pix / LTOK;
    int l = pix - b * LTOK;
    int y = l / WWID;
    int xw = l - y * WWID;
    int cbase = c4 * 4;

    const float4* in4 = (const float4*)xin;
    float a0 = 0.f, a1 = 0.f, a2 = 0.f, a3 = 0.f;
#pragma unroll
    for (int dy = -1; dy <= 1; dy++) {
        int yy = y + dy;
        if ((unsigned)yy >= (unsigned)HH) continue;
#pragma unroll
        for (int dx = -1; dx <= 1; dx++) {
            int xx = xw + dx;
            if ((unsigned)xx >= (unsigned)WWID) continue;
            float4 v = in4[((size_t)b * LTOK + yy * WWID + xx) * 96 + c4];
            int tap = (dy + 1) * 3 + (dx + 1);
            a0 += v.x * w[(cbase + 0) * 9 + tap];
            a1 += v.y * w[(cbase + 1) * 9 + tap];
            a2 += v.z * w[(cbase + 2) * 9 + tap];
            a3 += v.w * w[(cbase + 3) * 9 + tap];
        }
    }
    float4 o;
    o.x = (a0 - bnm[cbase + 0]) * rsqrtf(bnv[cbase + 0] + EPSV) * bng[cbase + 0] + bnb[cbase + 0];
    o.y = (a1 - bnm[cbase + 1]) * rsqrtf(bnv[cbase + 1] + EPSV) * bng[cbase + 1] + bnb[cbase + 1];
    o.z = (a2 - bnm[cbase + 2]) * rsqrtf(bnv[cbase + 2] + EPSV) * bng[cbase + 2] + bnb[cbase + 2];
    o.w = (a3 - bnm[cbase + 3]) * rsqrtf(bnv[cbase + 3] + EPSV) * bng[cbase + 3] + bnb[cbase + 3];
    ((float4*)out)[(size_t)pix * 96 + c4] = o;
}

// ---------------------------------------------------------------------------
// Launcher
// ---------------------------------------------------------------------------
extern "C" void kernel_launch(void* const* d_in, const int* in_sizes, int n_in,
                              void* d_out, int out_size)
{
    const float* x      = (const float*)d_in[0];
    const float* n1g    = (const float*)d_in[1];
    const float* n1b    = (const float*)d_in[2];
    const float* qkv_w  = (const float*)d_in[3];
    const float* qkv_b  = (const float*)d_in[4];
    const float* attn_b = (const float*)d_in[5];
    const int*   bidx   = (const int*)  d_in[6];
    const float* proj_w = (const float*)d_in[7];
    const float* proj_b = (const float*)d_in[8];
    const float* conv_w = (const float*)d_in[9];
    const float* bn_g   = (const float*)d_in[10];
    const float* bn_b   = (const float*)d_in[11];
    const float* bn_m   = (const float*)d_in[12];
    const float* bn_v   = (const float*)d_in[13];
    const float* n2g    = (const float*)d_in[14];
    const float* n2b    = (const float*)d_in[15];
    const float* fc1_w  = (const float*)d_in[16];
    const float* fc1_b  = (const float*)d_in[17];
    const float* fc2_w  = (const float*)d_in[18];
    const float* fc2_b  = (const float*)d_in[19];
    float* out = (float*)d_out;

    void* p;
    cudaGetSymbolAddress(&p, g_qkv); float* qkv = (float*)p;
    cudaGetSymbolAddress(&p, g_xh);  unsigned short* xh  = (unsigned short*)p;
    cudaGetSymbolAddress(&p, g_xl);  unsigned short* xl  = (unsigned short*)p;
    cudaGetSymbolAddress(&p, g_ath); unsigned short* ath = (unsigned short*)p;
    cudaGetSymbolAddress(&p, g_atl); unsigned short* atl = (unsigned short*)p;
    cudaGetSymbolAddress(&p, g_hh);  unsigned short* hh  = (unsigned short*)p;
    cudaGetSymbolAddress(&p, g_hl);  unsigned short* hl  = (unsigned short*)p;
    cudaGetSymbolAddress(&p, g_x1);  float* x1 = (float*)p;
    cudaGetSymbolAddress(&p, g_x2);  float* x2 = (float*)p;
    cudaGetSymbolAddress(&p, g_qwh); unsigned short* qwh = (unsigned short*)p;
    cudaGetSymbolAddress(&p, g_qwl); unsigned short* qwl = (unsigned short*)p;
    cudaGetSymbolAddress(&p, g_pwh); unsigned short* pwh = (unsigned short*)p;
    cudaGetSymbolAddress(&p, g_pwl); unsigned short* pwl = (unsigned short*)p;
    cudaGetSymbolAddress(&p, g_f1h); unsigned short* f1h = (unsigned short*)p;
    cudaGetSymbolAddress(&p, g_f1l); unsigned short* f1l = (unsigned short*)p;
    cudaGetSymbolAddress(&p, g_f2h); unsigned short* f2h = (unsigned short*)p;
    cudaGetSymbolAddress(&p, g_f2l); unsigned short* f2l = (unsigned short*)p;

    cudaFuncSetAttribute(tmma_gemm<0>, cudaFuncAttributeMaxDynamicSharedMemorySize, GSMEM_SZ);
    cudaFuncSetAttribute(tmma_gemm<1>, cudaFuncAttributeMaxDynamicSharedMemorySize, GSMEM_SZ);
    cudaFuncSetAttribute(tmma_gemm<2>, cudaFuncAttributeMaxDynamicSharedMemorySize, GSMEM_SZ);

    // 0. split weights (tiny)
    split_kernel<<<(1152 * CC + 255) / 256, 256>>>(qkv_w, qwh, qwl, 1152 * CC);
    split_kernel<<<(CC * CC + 255) / 256, 256>>>(proj_w, pwh, pwl, CC * CC);
    split_kernel<<<(MLPH * CC + 255) / 256, 256>>>(fc1_w, f1h, f1l, MLPH * CC);
    split_kernel<<<(CC * MLPH + 255) / 256, 256>>>(fc2_w, f2h, f2l, CC * MLPH);

    // 1. LN1 -> xn hi/lo
    ln_split_kernel<<<MTOK / 8, 256>>>(x, n1g, n1b, xh, xl);

    // 2. QKV GEMM: [50176,384]x[1152,384]^T + bias -> qkv fp32 (stride 1152)
    tmma_gemm<0><<<dim3(1152 / 128, MTOK / 128), 256, GSMEM_SZ>>>(
        xh, xl, qwh, qwl, qkv_b, nullptr, qkv, nullptr, nullptr, 1152, CC);

    // 3. window attention -> att hi/lo (natural token order): 12288 blocks
    attn_kernel<<<BB * 16 * HEADS, 128>>>(qkv, attn_b, bidx, ath, atl);

    // 4. proj + bias + residual x -> x1 fp32
    tmma_gemm<1><<<dim3(CC / 128, MTOK / 128), 256, GSMEM_SZ>>>(
        ath, atl, pwh, pwl, proj_b, x, x1, nullptr, nullptr, CC, CC);

    // 5. dwconv 3x3 + BN: x1 -> x2
    conv_bn_kernel<<<(MTOK * 96 + 255) / 256, 256>>>(x1, conv_w, bn_g, bn_b, bn_m, bn_v, x2);

    // 6. LN2 -> xn hi/lo (reuse)
    ln_split_kernel<<<MTOK / 8, 256>>>(x2, n2g, n2b, xh, xl);

    // 7. fc1 + bias + gelu -> h hi/lo
    tmma_gemm<2><<<dim3(MLPH / 128, MTOK / 128), 256, GSMEM_SZ>>>(
        xh, xl, f1h, f1l, fc1_b, nullptr, nullptr, hh, hl, MLPH, CC);

    // 8. fc2 + bias + residual x2 -> out
    tmma_gemm<1><<<dim3(CC / 128, MTOK / 128), 256, GSMEM_SZ>>>(
        hh, hl, f2h, f2l, fc2_b, x2, out, nullptr, nullptr, CC, MLPH);
}